// round 1
// baseline (speedup 1.0000x reference)
#include <cuda_runtime.h>
#include <cuda_bf16.h>
#include <stdint.h>

#define NUM_EXPERTS 8
#define HIDDEN 2048
#define INTER 1408
#define NTOK 8192

#define BM 64
#define BN 64
#define BK 32
#define SST 36            // smem row stride (floats), padded for conflict-free quad access
#define THREADS 256

#define MAX_MTILES (NTOK/BM + NUM_EXPERTS - 1)   // 135
#define NB1 (INTER/BN)    // 22
#define NB2 (HIDDEN/BN)   // 32

// -------- device scratch (allocation-free per harness rules) --------
__device__ int g_counts[NUM_EXPERTS];
__device__ int g_cursor[NUM_EXPERTS];
__device__ int g_offsets[NUM_EXPERTS + 1];
__device__ int g_mtoff[NUM_EXPERTS + 1];
__device__ int g_perm[NTOK];
__device__ float g_h[(size_t)NTOK * INTER];   // fp32 intermediate (46MB)

// -------- router --------
__global__ void k_reset() {
    int t = threadIdx.x;
    if (t < NUM_EXPERTS) { g_counts[t] = 0; g_cursor[t] = 0; }
}

__global__ void k_count(const int* __restrict__ ids) {
    int i = blockIdx.x * blockDim.x + threadIdx.x;
    if (i < NTOK) atomicAdd(&g_counts[ids[i]], 1);
}

__global__ void k_scan() {
    if (threadIdx.x == 0) {
        int off = 0, moff = 0;
        for (int e = 0; e < NUM_EXPERTS; e++) {
            g_offsets[e] = off; g_mtoff[e] = moff;
            off  += g_counts[e];
            moff += (g_counts[e] + BM - 1) / BM;
        }
        g_offsets[NUM_EXPERTS] = off;
        g_mtoff[NUM_EXPERTS]   = moff;
    }
}

__global__ void k_scatter(const int* __restrict__ ids) {
    int i = blockIdx.x * blockDim.x + threadIdx.x;
    if (i < NTOK) {
        int e = ids[i];
        int pos = g_offsets[e] + atomicAdd(&g_cursor[e], 1);
        g_perm[pos] = i;
    }
}

// -------- helpers --------
__device__ __forceinline__ float to_tf32(float x) {
    uint32_t u;
    asm("cvt.rna.tf32.f32 %0, %1;" : "=r"(u) : "f"(x));
    return __uint_as_float(u);
}
__device__ __forceinline__ uint32_t fu(float x) { return __float_as_uint(x); }

__device__ __forceinline__ void mma_tf32(float c[4],
        uint32_t a0, uint32_t a1, uint32_t a2, uint32_t a3,
        uint32_t b0, uint32_t b1) {
    asm volatile(
        "mma.sync.aligned.m16n8k8.row.col.f32.tf32.tf32.f32 "
        "{%0,%1,%2,%3},{%4,%5,%6,%7},{%8,%9},{%0,%1,%2,%3};\n"
        : "+f"(c[0]), "+f"(c[1]), "+f"(c[2]), "+f"(c[3])
        : "r"(a0), "r"(a1), "r"(a2), "r"(a3), "r"(b0), "r"(b1));
}

// Decode flat tile id -> (expert, n_tile, m_tile). Tiles of an expert are
// contiguous so its A-panel stays L2-resident while B streams once.
__device__ __forceinline__ bool decode_tile(int bx, int NB,
        int& e, int& nt, int& m_start, int& valid) {
    int total = g_mtoff[NUM_EXPERTS] * NB;
    if (bx >= total) return false;
    e = 0;
    while (bx >= g_mtoff[e + 1] * NB) e++;
    int local = bx - g_mtoff[e] * NB;
    int mt = g_mtoff[e + 1] - g_mtoff[e];
    nt = local / mt;
    int ml = local % mt;
    m_start = g_offsets[e] + ml * BM;
    valid = g_offsets[e + 1] - m_start;
    if (valid > BM) valid = BM;
    return true;
}

// -------- GEMM1: h = silu(x@Wg^T) * (x@Wu^T) * weight, grouped by expert --------
__global__ void __launch_bounds__(THREADS)
k_gemm1(const float* __restrict__ tokens,
        const float* __restrict__ gu,        // [E, 2I, D]
        const float* __restrict__ wts) {
    __shared__ float As[BM * SST];
    __shared__ float Bg[BN * SST];
    __shared__ float Bu[BN * SST];

    int e, nt, m_start, valid;
    if (!decode_tile(blockIdx.x, NB1, e, nt, m_start, valid)) return;

    const int tid  = threadIdx.x;
    const int lane = tid & 31;
    const int wm   = (tid >> 5) >> 2;   // 0..1
    const int wn   = (tid >> 5) & 3;    // 0..3

    // global-load mapping: row = tid/4 (64 rows), col0 = (tid%4)*8
    const int lrow = tid >> 2;
    const int lc0  = (tid & 3) * 8;
    const int srow = (lrow < valid) ? lrow : (valid - 1);
    const int tok  = g_perm[m_start + srow];

    const float* aptr  = tokens + (size_t)tok * HIDDEN + lc0;
    const size_t gbase = (size_t)e * (2 * INTER) * HIDDEN;
    const int nrow     = nt * BN + lrow;
    const float* bgptr = gu + gbase + (size_t)nrow * HIDDEN + lc0;
    const float* buptr = gu + gbase + (size_t)(nrow + INTER) * HIDDEN + lc0;

    float accg[2][2][4] = {};
    float accu[2][2][4] = {};

    for (int k0 = 0; k0 < HIDDEN; k0 += BK) {
        float4 a0 = *(const float4*)(aptr + k0);
        float4 a1 = *(const float4*)(aptr + k0 + 4);
        float4 g0 = *(const float4*)(bgptr + k0);
        float4 g1 = *(const float4*)(bgptr + k0 + 4);
        float4 u0 = *(const float4*)(buptr + k0);
        float4 u1 = *(const float4*)(buptr + k0 + 4);

        float* ad = &As[lrow * SST + lc0];
        ad[0]=to_tf32(a0.x); ad[1]=to_tf32(a0.y); ad[2]=to_tf32(a0.z); ad[3]=to_tf32(a0.w);
        ad[4]=to_tf32(a1.x); ad[5]=to_tf32(a1.y); ad[6]=to_tf32(a1.z); ad[7]=to_tf32(a1.w);
        float* gd = &Bg[lrow * SST + lc0];
        gd[0]=to_tf32(g0.x); gd[1]=to_tf32(g0.y); gd[2]=to_tf32(g0.z); gd[3]=to_tf32(g0.w);
        gd[4]=to_tf32(g1.x); gd[5]=to_tf32(g1.y); gd[6]=to_tf32(g1.z); gd[7]=to_tf32(g1.w);
        float* ud = &Bu[lrow * SST + lc0];
        ud[0]=to_tf32(u0.x); ud[1]=to_tf32(u0.y); ud[2]=to_tf32(u0.z); ud[3]=to_tf32(u0.w);
        ud[4]=to_tf32(u1.x); ud[5]=to_tf32(u1.y); ud[6]=to_tf32(u1.z); ud[7]=to_tf32(u1.w);
        __syncthreads();

        #pragma unroll
        for (int ks = 0; ks < BK / 8; ks++) {
            const int kk = ks * 8 + (lane & 3);
            uint32_t a[2][4];
            #pragma unroll
            for (int im = 0; im < 2; im++) {
                int ar = wm * 32 + im * 16 + (lane >> 2);
                a[im][0] = fu(As[ar * SST + kk]);
                a[im][1] = fu(As[(ar + 8) * SST + kk]);
                a[im][2] = fu(As[ar * SST + kk + 4]);
                a[im][3] = fu(As[(ar + 8) * SST + kk + 4]);
            }
            #pragma unroll
            for (int jn = 0; jn < 2; jn++) {
                int br = wn * 16 + jn * 8 + (lane >> 2);
                uint32_t bg0 = fu(Bg[br * SST + kk]);
                uint32_t bg1 = fu(Bg[br * SST + kk + 4]);
                uint32_t bu0 = fu(Bu[br * SST + kk]);
                uint32_t bu1 = fu(Bu[br * SST + kk + 4]);
                #pragma unroll
                for (int im = 0; im < 2; im++) {
                    mma_tf32(accg[im][jn], a[im][0], a[im][1], a[im][2], a[im][3], bg0, bg1);
                    mma_tf32(accu[im][jn], a[im][0], a[im][1], a[im][2], a[im][3], bu0, bu1);
                }
            }
        }
        __syncthreads();
    }

    // epilogue: silu(g)*u*weight -> g_h (fp32, rows in sorted order)
    #pragma unroll
    for (int im = 0; im < 2; im++) {
        #pragma unroll
        for (int jn = 0; jn < 2; jn++) {
            int r0 = wm * 32 + im * 16 + (lane >> 2);
            int cb = nt * BN + wn * 16 + jn * 8 + (lane & 3) * 2;
            #pragma unroll
            for (int half = 0; half < 2; half++) {
                int r = r0 + half * 8;
                if (r < valid) {
                    int s = m_start + r;
                    float wt = wts[g_perm[s]];
                    float* dst = &g_h[(size_t)s * INTER + cb];
                    #pragma unroll
                    for (int cc = 0; cc < 2; cc++) {
                        float g = accg[im][jn][half * 2 + cc];
                        float u = accu[im][jn][half * 2 + cc];
                        float sg = g / (1.0f + __expf(-g));
                        dst[cc] = sg * u * wt;
                    }
                }
            }
        }
    }
}

// -------- GEMM2: out[perm[s]] = h[s] @ down[e]^T, grouped by expert --------
__global__ void __launch_bounds__(THREADS)
k_gemm2(const float* __restrict__ down,     // [E, D, I]
        float* __restrict__ out) {
    __shared__ float As[BM * SST];
    __shared__ float Bs[BN * SST];

    int e, nt, m_start, valid;
    if (!decode_tile(blockIdx.x, NB2, e, nt, m_start, valid)) return;

    const int tid  = threadIdx.x;
    const int lane = tid & 31;
    const int wm   = (tid >> 5) >> 2;
    const int wn   = (tid >> 5) & 3;

    const int lrow = tid >> 2;
    const int lc0  = (tid & 3) * 8;
    const int srow = (lrow < valid) ? lrow : (valid - 1);

    const float* aptr = g_h + (size_t)(m_start + srow) * INTER + lc0;
    const float* bptr = down + (size_t)e * HIDDEN * INTER
                             + (size_t)(nt * BN + lrow) * INTER + lc0;

    float acc[2][2][4] = {};

    for (int k0 = 0; k0 < INTER; k0 += BK) {
        float4 a0 = *(const float4*)(aptr + k0);
        float4 a1 = *(const float4*)(aptr + k0 + 4);
        float4 b0 = *(const float4*)(bptr + k0);
        float4 b1 = *(const float4*)(bptr + k0 + 4);

        float* ad = &As[lrow * SST + lc0];
        ad[0]=to_tf32(a0.x); ad[1]=to_tf32(a0.y); ad[2]=to_tf32(a0.z); ad[3]=to_tf32(a0.w);
        ad[4]=to_tf32(a1.x); ad[5]=to_tf32(a1.y); ad[6]=to_tf32(a1.z); ad[7]=to_tf32(a1.w);
        float* bd = &Bs[lrow * SST + lc0];
        bd[0]=to_tf32(b0.x); bd[1]=to_tf32(b0.y); bd[2]=to_tf32(b0.z); bd[3]=to_tf32(b0.w);
        bd[4]=to_tf32(b1.x); bd[5]=to_tf32(b1.y); bd[6]=to_tf32(b1.z); bd[7]=to_tf32(b1.w);
        __syncthreads();

        #pragma unroll
        for (int ks = 0; ks < BK / 8; ks++) {
            const int kk = ks * 8 + (lane & 3);
            uint32_t a[2][4];
            #pragma unroll
            for (int im = 0; im < 2; im++) {
                int ar = wm * 32 + im * 16 + (lane >> 2);
                a[im][0] = fu(As[ar * SST + kk]);
                a[im][1] = fu(As[(ar + 8) * SST + kk]);
                a[im][2] = fu(As[ar * SST + kk + 4]);
                a[im][3] = fu(As[(ar + 8) * SST + kk + 4]);
            }
            #pragma unroll
            for (int jn = 0; jn < 2; jn++) {
                int br = wn * 16 + jn * 8 + (lane >> 2);
                uint32_t bb0 = fu(Bs[br * SST + kk]);
                uint32_t bb1 = fu(Bs[br * SST + kk + 4]);
                #pragma unroll
                for (int im = 0; im < 2; im++) {
                    mma_tf32(acc[im][jn], a[im][0], a[im][1], a[im][2], a[im][3], bb0, bb1);
                }
            }
        }
        __syncthreads();
    }

    #pragma unroll
    for (int im = 0; im < 2; im++) {
        #pragma unroll
        for (int jn = 0; jn < 2; jn++) {
            int r0 = wm * 32 + im * 16 + (lane >> 2);
            int cb = nt * BN + wn * 16 + jn * 8 + (lane & 3) * 2;
            #pragma unroll
            for (int half = 0; half < 2; half++) {
                int r = r0 + half * 8;
                if (r < valid) {
                    int s = m_start + r;
                    int tok = g_perm[s];
                    float* dst = out + (size_t)tok * HIDDEN + cb;
                    dst[0] = acc[im][jn][half * 2 + 0];
                    dst[1] = acc[im][jn][half * 2 + 1];
                }
            }
        }
    }
}

// -------- launch --------
extern "C" void kernel_launch(void* const* d_in, const int* in_sizes, int n_in,
                              void* d_out, int out_size) {
    const float* tokens = (const float*)d_in[0];
    const int*   ids    = (const int*)d_in[1];
    const float* wts    = (const float*)d_in[2];
    const float* gu     = (const float*)d_in[3];
    const float* down   = (const float*)d_in[4];
    float* out = (float*)d_out;

    k_reset<<<1, 32>>>();
    k_count<<<NTOK / 256, 256>>>(ids);
    k_scan<<<1, 32>>>();
    k_scatter<<<NTOK / 256, 256>>>(ids);

    k_gemm1<<<MAX_MTILES * NB1, THREADS>>>(tokens, gu, wts);
    k_gemm2<<<MAX_MTILES * NB2, THREADS>>>(down, out);
}